// round 2
// baseline (speedup 1.0000x reference)
#include <cuda_runtime.h>
#include <cuda_bf16.h>
#include <cstdint>

// Problem constants (static shapes from reference)
#define PB   256            // graphs
#define PN   512            // nodes per graph
#define PD   256            // channels
#define PDEG 32
#define PE   (PB * PN * PDEG)     // 4,194,304 edges
#define PNN  (PB * PN)            // 131,072 nodes
#define PK   409                  // kept nodes per graph
#define PBK  (PB * PK)            // 104,704 kept nodes total

// Output layout (float32, concatenated in reference return order)
#define OFF_X     ((size_t)0)
#define OFF_EI    ((size_t)PBK * PD)                 // 26,804,224
#define OFF_MASK  (OFF_EI + (size_t)2 * PE)          // 35,192,832
#define OFF_BATCH (OFF_MASK + (size_t)PE)            // 39,387,136
#define OFF_PERM  (OFF_BATCH + (size_t)PBK)          // 39,491,840

// Scratch (device globals: no allocation allowed)
__device__ float g_h[PNN];
__device__ float g_score[PNN];
__device__ int   g_deg[PNN];
__device__ int   g_keepmap[PNN];
__device__ int   g_perm[PBK];

// ---------------------------------------------------------------------------
// 1) init: deg=1 (self loop), score accumulator = 0
__global__ void k_init() {
    int v = blockIdx.x * blockDim.x + threadIdx.x;
    if (v < PNN) { g_deg[v] = 1; g_score[v] = 0.0f; }
}

// ---------------------------------------------------------------------------
// 2) h[v] = dot(x[v,:], W)  — warp per row, float4 loads
__global__ void k_h(const float* __restrict__ x, const float* __restrict__ W) {
    __shared__ float4 sW[PD / 4];
    int tid = threadIdx.x;
    if (tid < PD / 4) sW[tid] = reinterpret_cast<const float4*>(W)[tid];
    __syncthreads();
    int warp = tid >> 5, lane = tid & 31;
    int row = blockIdx.x * (blockDim.x >> 5) + warp;
    if (row >= PNN) return;
    const float4* xr = reinterpret_cast<const float4*>(x + (size_t)row * PD);
    float4 a = xr[lane];
    float4 b = xr[lane + 32];
    float4 wa = sW[lane];
    float4 wb = sW[lane + 32];
    float s = a.x * wa.x + a.y * wa.y + a.z * wa.z + a.w * wa.w
            + b.x * wb.x + b.y * wb.y + b.z * wb.z + b.w * wb.w;
    #pragma unroll
    for (int o = 16; o > 0; o >>= 1) s += __shfl_down_sync(0xffffffffu, s, o);
    if (lane == 0) g_h[row] = s;
}

// ---------------------------------------------------------------------------
// 3) degree count over col
__global__ void k_deg(const int* __restrict__ ei) {
    int e = blockIdx.x * blockDim.x + threadIdx.x;
    if (e < PE) atomicAdd(&g_deg[ei[PE + e]], 1);
}

// ---------------------------------------------------------------------------
// 4) scatter: score[col] += rsqrt(deg[row])*rsqrt(deg[col]) * h[row]
__global__ void k_scatter(const int* __restrict__ ei) {
    int e = blockIdx.x * blockDim.x + threadIdx.x;
    if (e >= PE) return;
    int r = ei[e];
    int c = ei[PE + e];
    float nrm = rsqrtf((float)g_deg[r]) * rsqrtf((float)g_deg[c]);
    atomicAdd(&g_score[c], nrm * g_h[r]);
}

// ---------------------------------------------------------------------------
// 5) per-graph: finalize score, top-K via bitonic sort, ranks via scan
__device__ __forceinline__ unsigned int fkey(float f) {
    unsigned int u = __float_as_uint(f);
    return (u & 0x80000000u) ? ~u : (u | 0x80000000u);   // monotonic mapping
}

__global__ void k_topk(const float* __restrict__ bvec, float* __restrict__ out) {
    __shared__ unsigned long long sk[PN];
    __shared__ int flag[PN];
    __shared__ int scan[PN];
    int g = blockIdx.x;
    int t = threadIdx.x;          // 512 threads
    int v = g * PN + t;

    float s = g_score[v] + g_h[v] / (float)g_deg[v] + bvec[0];
    g_score[v] = s;               // final score, used by x_out kernel

    // key: ascending sort; ties in score -> larger (511-idx) i.e. smaller idx
    // sorts toward the top (kept) end => matches top_k lowest-index tiebreak.
    sk[t] = (((unsigned long long)fkey(s)) << 9) | (unsigned long long)(511 - t);
    flag[t] = 0;
    __syncthreads();

    // bitonic sort ascending (512 elements, 512 threads)
    for (unsigned int k = 2; k <= PN; k <<= 1) {
        for (unsigned int j = k >> 1; j > 0; j >>= 1) {
            unsigned int i = (unsigned int)t;
            unsigned int ixj = i ^ j;
            if (ixj > i) {
                bool up = ((i & k) == 0);
                unsigned long long a = sk[i], b = sk[ixj];
                if (up ? (a > b) : (a < b)) { sk[i] = b; sk[ixj] = a; }
            }
            __syncthreads();
        }
    }

    // top K keys occupy positions [N-K, N)
    if (t >= PN - PK) {
        int li = 511 - (int)(sk[t] & 511ull);
        flag[li] = 1;
    }
    __syncthreads();

    // Hillis-Steele inclusive scan of flags
    scan[t] = flag[t];
    __syncthreads();
    #pragma unroll
    for (int d = 1; d < PN; d <<= 1) {
        int add = (t >= d) ? scan[t - d] : 0;
        __syncthreads();
        scan[t] += add;
        __syncthreads();
    }

    if (flag[t]) {
        int rank = scan[t] - 1;
        int gi = g * PK + rank;
        g_keepmap[v] = gi;
        g_perm[gi] = v;
        out[OFF_PERM + gi]  = (float)v;
        out[OFF_BATCH + gi] = (float)g;
    } else {
        g_keepmap[v] = -1;
    }
}

// ---------------------------------------------------------------------------
// 6) x_out[i] = x[perm[i]] * tanh(score[perm[i]])  — warp per row
__global__ void k_xout(const float* __restrict__ x, float* __restrict__ out) {
    int tid = threadIdx.x;
    int warp = tid >> 5, lane = tid & 31;
    int row = blockIdx.x * (blockDim.x >> 5) + warp;
    if (row >= PBK) return;
    int p = g_perm[row];
    float tsc = tanhf(g_score[p]);
    const float4* xr = reinterpret_cast<const float4*>(x + (size_t)p * PD);
    float4* orow = reinterpret_cast<float4*>(out + OFF_X + (size_t)row * PD);
    float4 a = xr[lane];
    float4 b = xr[lane + 32];
    a.x *= tsc; a.y *= tsc; a.z *= tsc; a.w *= tsc;
    b.x *= tsc; b.y *= tsc; b.z *= tsc; b.w *= tsc;
    orow[lane] = a;
    orow[lane + 32] = b;
}

// ---------------------------------------------------------------------------
// 7) edge relabel + mask
__global__ void k_edges(const int* __restrict__ ei, float* __restrict__ out) {
    int e = blockIdx.x * blockDim.x + threadIdx.x;
    if (e >= PE) return;
    int r = ei[e];
    int c = ei[PE + e];
    int a = g_keepmap[r];
    int b = g_keepmap[c];
    bool m = (a >= 0) && (b >= 0);
    out[OFF_EI + e]              = m ? (float)a : -1.0f;
    out[OFF_EI + (size_t)PE + e] = m ? (float)b : -1.0f;
    out[OFF_MASK + e]            = m ? 1.0f : 0.0f;
}

// ---------------------------------------------------------------------------
extern "C" void kernel_launch(void* const* d_in, const int* in_sizes, int n_in,
                              void* d_out, int out_size) {
    const float* x  = (const float*)d_in[0];   // [131072, 256]
    const int*   ei = (const int*)d_in[1];     // [2, E]
    // d_in[2] = batch (unused: batch_out derivable as g)
    const float* W  = (const float*)d_in[3];   // [256, 1]
    const float* b  = (const float*)d_in[4];   // [1]
    float* out = (float*)d_out;

    k_init<<<(PNN + 255) / 256, 256>>>();
    k_h<<<PNN / 8, 256>>>(x, W);
    k_deg<<<PE / 256, 256>>>(ei);
    k_scatter<<<PE / 256, 256>>>(ei);
    k_topk<<<PB, PN>>>(b, out);
    k_xout<<<(PBK + 7) / 8, 256>>>(x, out);
    k_edges<<<PE / 256, 256>>>(ei, out);
}

// round 4
// speedup vs baseline: 1.1567x; 1.1567x over previous
#include <cuda_runtime.h>
#include <cuda_bf16.h>
#include <cstdint>

// Problem constants (static shapes from reference)
#define PB   256
#define PN   512
#define PD   256
#define PDEG 32
#define PE   (PB * PN * PDEG)     // 4,194,304 edges
#define PNN  (PB * PN)            // 131,072 nodes
#define PK   409
#define PBK  (PB * PK)            // 104,704

// Output layout (float32, concatenated in reference return order)
#define OFF_X     ((size_t)0)
#define OFF_EI    ((size_t)PBK * PD)
#define OFF_MASK  (OFF_EI + (size_t)2 * PE)
#define OFF_BATCH (OFF_MASK + (size_t)PE)
#define OFF_PERM  (OFF_BATCH + (size_t)PBK)

// Scratch (device globals)
__device__ float g_h[PNN];
__device__ float g_u[PNN];       // dinv[v] * h[v]
__device__ float g_acc[PNN];     // sum over in-edges of u[row]
__device__ float g_score[PNN];   // final score
__device__ int   g_deg[PNN];
__device__ int   g_keepmap[PNN];
__device__ int   g_perm[PBK];

// ---------------------------------------------------------------------------
// 1) h[v] = dot(x[v,:], W), fused with deg/acc init. Warp per row.
__global__ void k_h(const float* __restrict__ x, const float* __restrict__ W) {
    __shared__ float4 sW[PD / 4];
    int tid = threadIdx.x;
    if (tid < PD / 4) sW[tid] = reinterpret_cast<const float4*>(W)[tid];
    __syncthreads();
    int warp = tid >> 5, lane = tid & 31;
    int base = blockIdx.x * 8;
    if (tid < 8) { g_deg[base + tid] = 1; g_acc[base + tid] = 0.0f; }
    int row = base + warp;
    const float4* xr = reinterpret_cast<const float4*>(x + (size_t)row * PD);
    float4 a = xr[lane];
    float4 b = xr[lane + 32];
    float4 wa = sW[lane];
    float4 wb = sW[lane + 32];
    float s = a.x * wa.x + a.y * wa.y + a.z * wa.z + a.w * wa.w
            + b.x * wb.x + b.y * wb.y + b.z * wb.z + b.w * wb.w;
    #pragma unroll
    for (int o = 16; o > 0; o >>= 1) s += __shfl_down_sync(0xffffffffu, s, o);
    if (lane == 0) g_h[row] = s;
}

// ---------------------------------------------------------------------------
// 2) degree count over col — 4 edges/thread for MLP
__global__ void k_deg(const int* __restrict__ ei) {
    int t = blockIdx.x * blockDim.x + threadIdx.x;   // t in [0, PE/4)
    int4 c = reinterpret_cast<const int4*>(ei + PE)[t];
    atomicAdd(&g_deg[c.x], 1);
    atomicAdd(&g_deg[c.y], 1);
    atomicAdd(&g_deg[c.z], 1);
    atomicAdd(&g_deg[c.w], 1);
}

// ---------------------------------------------------------------------------
// 3) u[v] = rsqrt(deg[v]) * h[v]
__global__ void k_u() {
    int v = blockIdx.x * blockDim.x + threadIdx.x;
    if (v < PNN) g_u[v] = rsqrtf((float)g_deg[v]) * g_h[v];
}

// ---------------------------------------------------------------------------
// 4) acc[col] += u[row] — 4 edges/thread
__global__ void k_scatter(const int* __restrict__ ei) {
    int t = blockIdx.x * blockDim.x + threadIdx.x;   // t in [0, PE/4)
    int4 r = reinterpret_cast<const int4*>(ei)[t];
    int4 c = reinterpret_cast<const int4*>(ei + PE)[t];
    float u0 = g_u[r.x];
    float u1 = g_u[r.y];
    float u2 = g_u[r.z];
    float u3 = g_u[r.w];
    atomicAdd(&g_acc[c.x], u0);
    atomicAdd(&g_acc[c.y], u1);
    atomicAdd(&g_acc[c.z], u2);
    atomicAdd(&g_acc[c.w], u3);
}

// ---------------------------------------------------------------------------
// 5) per-graph: finalize score, top-K via bitonic sort, ranks via scan
__device__ __forceinline__ unsigned int fkey(float f) {
    unsigned int u = __float_as_uint(f);
    return (u & 0x80000000u) ? ~u : (u | 0x80000000u);
}

__global__ void k_topk(const float* __restrict__ bvec, float* __restrict__ out) {
    __shared__ unsigned long long sk[PN];
    __shared__ int flag[PN];
    __shared__ int scan[PN];
    int g = blockIdx.x;
    int t = threadIdx.x;
    int v = g * PN + t;

    // score = dinv*(acc + u) + b   (self-loop term = dinv*u)
    float s = rsqrtf((float)g_deg[v]) * (g_acc[v] + g_u[v]) + bvec[0];
    g_score[v] = s;

    sk[t] = (((unsigned long long)fkey(s)) << 9) | (unsigned long long)(511 - t);
    flag[t] = 0;
    __syncthreads();

    for (unsigned int k = 2; k <= PN; k <<= 1) {
        for (unsigned int j = k >> 1; j > 0; j >>= 1) {
            unsigned int i = (unsigned int)t;
            unsigned int ixj = i ^ j;
            if (ixj > i) {
                bool up = ((i & k) == 0);
                unsigned long long a = sk[i], b = sk[ixj];
                if (up ? (a > b) : (a < b)) { sk[i] = b; sk[ixj] = a; }
            }
            __syncthreads();
        }
    }

    if (t >= PN - PK) {
        int li = 511 - (int)(sk[t] & 511ull);
        flag[li] = 1;
    }
    __syncthreads();

    scan[t] = flag[t];
    __syncthreads();
    #pragma unroll
    for (int d = 1; d < PN; d <<= 1) {
        int add = (t >= d) ? scan[t - d] : 0;
        __syncthreads();
        scan[t] += add;
        __syncthreads();
    }

    if (flag[t]) {
        int rank = scan[t] - 1;
        int gi = g * PK + rank;
        g_keepmap[v] = gi;
        g_perm[gi] = v;
        out[OFF_PERM + gi]  = (float)v;
        out[OFF_BATCH + gi] = (float)g;
    } else {
        g_keepmap[v] = -1;
    }
}

// ---------------------------------------------------------------------------
// 6) x_out[i] = x[perm[i]] * tanh(score[perm[i]]) — warp per row
__global__ void k_xout(const float* __restrict__ x, float* __restrict__ out) {
    int tid = threadIdx.x;
    int warp = tid >> 5, lane = tid & 31;
    int row = blockIdx.x * (blockDim.x >> 5) + warp;
    if (row >= PBK) return;
    int p = g_perm[row];
    float tsc = tanhf(g_score[p]);
    const float4* xr = reinterpret_cast<const float4*>(x + (size_t)p * PD);
    float4* orow = reinterpret_cast<float4*>(out + OFF_X + (size_t)row * PD);
    float4 a = xr[lane];
    float4 b = xr[lane + 32];
    a.x *= tsc; a.y *= tsc; a.z *= tsc; a.w *= tsc;
    b.x *= tsc; b.y *= tsc; b.z *= tsc; b.w *= tsc;
    orow[lane] = a;
    orow[lane + 32] = b;
}

// ---------------------------------------------------------------------------
// 7) edge relabel + mask — 4 edges/thread, float4 stores
__global__ void k_edges(const int* __restrict__ ei, float* __restrict__ out) {
    int t = blockIdx.x * blockDim.x + threadIdx.x;   // t in [0, PE/4)
    int4 r = reinterpret_cast<const int4*>(ei)[t];
    int4 c = reinterpret_cast<const int4*>(ei + PE)[t];
    int a0 = g_keepmap[r.x], a1 = g_keepmap[r.y], a2 = g_keepmap[r.z], a3 = g_keepmap[r.w];
    int b0 = g_keepmap[c.x], b1 = g_keepmap[c.y], b2 = g_keepmap[c.z], b3 = g_keepmap[c.w];
    bool m0 = (a0 >= 0) && (b0 >= 0);
    bool m1 = (a1 >= 0) && (b1 >= 0);
    bool m2 = (a2 >= 0) && (b2 >= 0);
    bool m3 = (a3 >= 0) && (b3 >= 0);
    float4 fr, fc, fm;
    fr.x = m0 ? (float)a0 : -1.0f;  fc.x = m0 ? (float)b0 : -1.0f;  fm.x = m0 ? 1.0f : 0.0f;
    fr.y = m1 ? (float)a1 : -1.0f;  fc.y = m1 ? (float)b1 : -1.0f;  fm.y = m1 ? 1.0f : 0.0f;
    fr.z = m2 ? (float)a2 : -1.0f;  fc.z = m2 ? (float)b2 : -1.0f;  fm.z = m2 ? 1.0f : 0.0f;
    fr.w = m3 ? (float)a3 : -1.0f;  fc.w = m3 ? (float)b3 : -1.0f;  fm.w = m3 ? 1.0f : 0.0f;
    reinterpret_cast<float4*>(out + OFF_EI)[t]              = fr;
    reinterpret_cast<float4*>(out + OFF_EI + (size_t)PE)[t] = fc;
    reinterpret_cast<float4*>(out + OFF_MASK)[t]            = fm;
}

// ---------------------------------------------------------------------------
extern "C" void kernel_launch(void* const* d_in, const int* in_sizes, int n_in,
                              void* d_out, int out_size) {
    const float* x  = (const float*)d_in[0];
    const int*   ei = (const int*)d_in[1];
    const float* W  = (const float*)d_in[3];
    const float* b  = (const float*)d_in[4];
    float* out = (float*)d_out;

    k_h<<<PNN / 8, 256>>>(x, W);
    k_deg<<<(PE / 4) / 256, 256>>>(ei);
    k_u<<<PNN / 256, 256>>>();
    k_scatter<<<(PE / 4) / 256, 256>>>(ei);
    k_topk<<<PB, PN>>>(b, out);
    k_xout<<<(PBK + 7) / 8, 256>>>(x, out);
    k_edges<<<(PE / 4) / 256, 256>>>(ei, out);
}

// round 6
// speedup vs baseline: 1.8423x; 1.5926x over previous
#include <cuda_runtime.h>
#include <cuda_bf16.h>
#include <cstdint>

#define PB   256
#define PN   512
#define PD   256
#define PDEG 32
#define PEG  (PN * PDEG)          // 16,384 edges per graph
#define PE   (PB * PEG)           // 4,194,304 edges
#define PNN  (PB * PN)            // 131,072 nodes
#define PK   409
#define PBK  (PB * PK)            // 104,704

// Output layout (float32, concatenated in reference return order)
#define OFF_X     ((size_t)0)
#define OFF_EI    ((size_t)PBK * PD)
#define OFF_MASK  (OFF_EI + (size_t)2 * PE)
#define OFF_BATCH (OFF_MASK + (size_t)PE)
#define OFF_PERM  (OFF_BATCH + (size_t)PBK)

__device__ __forceinline__ unsigned int fkey(float f) {
    unsigned int u = __float_as_uint(f);
    return (u & 0x80000000u) ? ~u : (u | 0x80000000u);   // monotonic float->uint
}

// One CTA per graph. All intermediates live in shared memory.
__global__ void __launch_bounds__(512, 2)
k_fused(const float* __restrict__ x, const int* __restrict__ ei,
        const float* __restrict__ W, const float* __restrict__ bias,
        float* __restrict__ out) {
    __shared__ float4 sW4[PD / 4];                // 1 KB
    __shared__ float  sh[PN];                     // h, then u (in place)
    __shared__ float  sacc[PN];
    __shared__ int    sdeg[PN];
    __shared__ float  sscore[PN];
    __shared__ unsigned long long sk[PN];         // 4 KB sort keys
    __shared__ int    sflag[PN];
    __shared__ int    sscan[PN];
    __shared__ int    skeep[PN];                  // global new idx or -1
    __shared__ int    sperm[PK];                  // rank -> local node idx

    const int g    = blockIdx.x;
    const int t    = threadIdx.x;                 // 0..511
    const int warp = t >> 5, lane = t & 31;

    // edge pointers for this graph (int4-aligned: g*PEG % 4 == 0)
    const int4* row4 = reinterpret_cast<const int4*>(ei + (size_t)g * PEG);
    const int4* col4 = reinterpret_cast<const int4*>(ei + (size_t)PE + (size_t)g * PEG);

    // ---- Phase 0: init + W load ----
    if (t < PD / 4) sW4[t] = reinterpret_cast<const float4*>(W)[t];
    sdeg[t] = 1;                                  // self loop
    sacc[t] = 0.0f;
    sflag[t] = 0;
    __syncthreads();

    // ---- Phase 1: h[v] = dot(x[v,:], W)  — warp per row, 32 rows/warp ----
    {
        const float4* xg = reinterpret_cast<const float4*>(x + (size_t)g * PN * PD);
        #pragma unroll 4
        for (int i = 0; i < PN / 16; i++) {       // 32 iterations
            int row = warp * 32 + i;
            const float4* xr = xg + (size_t)row * (PD / 4);
            float4 a = xr[lane];
            float4 b = xr[lane + 32];
            float4 wa = sW4[lane];
            float4 wb = sW4[lane + 32];
            float s = a.x * wa.x + a.y * wa.y + a.z * wa.z + a.w * wa.w
                    + b.x * wb.x + b.y * wb.y + b.z * wb.z + b.w * wb.w;
            #pragma unroll
            for (int o = 16; o > 0; o >>= 1) s += __shfl_down_sync(0xffffffffu, s, o);
            if (lane == 0) sh[row] = s;
        }
    }
    __syncthreads();   // sdeg ready for edge atomics; sh complete

    // ---- Phase 2: degree count (shared atomics) ----
    #pragma unroll
    for (int i = 0; i < PEG / 4 / PN; i++) {      // 8 iterations
        int4 c = col4[t + i * PN];
        atomicAdd(&sdeg[c.x & (PN - 1)], 1);
        atomicAdd(&sdeg[c.y & (PN - 1)], 1);
        atomicAdd(&sdeg[c.z & (PN - 1)], 1);
        atomicAdd(&sdeg[c.w & (PN - 1)], 1);
    }
    __syncthreads();

    // ---- Phase 3: u[v] = rsqrt(deg)*h  (in place over sh) ----
    sh[t] = rsqrtf((float)sdeg[t]) * sh[t];
    __syncthreads();

    // ---- Phase 4: acc[col] += u[row]  (shared gather + shared atomics) ----
    #pragma unroll
    for (int i = 0; i < PEG / 4 / PN; i++) {
        int idx = t + i * PN;
        int4 r = row4[idx];
        int4 c = col4[idx];
        float u0 = sh[r.x & (PN - 1)];
        float u1 = sh[r.y & (PN - 1)];
        float u2 = sh[r.z & (PN - 1)];
        float u3 = sh[r.w & (PN - 1)];
        atomicAdd(&sacc[c.x & (PN - 1)], u0);
        atomicAdd(&sacc[c.y & (PN - 1)], u1);
        atomicAdd(&sacc[c.z & (PN - 1)], u2);
        atomicAdd(&sacc[c.w & (PN - 1)], u3);
    }
    __syncthreads();

    // ---- Phase 5: score + bitonic top-K ----
    float s = rsqrtf((float)sdeg[t]) * (sacc[t] + sh[t]) + __ldg(bias);
    sscore[t] = s;
    // ascending sort; ties -> smaller node idx wins (matches top_k)
    sk[t] = (((unsigned long long)fkey(s)) << 9) | (unsigned long long)(511 - t);
    __syncthreads();

    for (unsigned int k = 2; k <= PN; k <<= 1) {
        for (unsigned int j = k >> 1; j > 0; j >>= 1) {
            unsigned int i = (unsigned int)t;
            unsigned int ixj = i ^ j;
            if (ixj > i) {
                bool up = ((i & k) == 0);
                unsigned long long a = sk[i], b = sk[ixj];
                if (up ? (a > b) : (a < b)) { sk[i] = b; sk[ixj] = a; }
            }
            __syncthreads();
        }
    }

    if (t >= PN - PK) {
        int li = 511 - (int)(sk[t] & 511ull);
        sflag[li] = 1;
    }
    __syncthreads();

    // Hillis-Steele inclusive scan of flags -> ranks
    sscan[t] = sflag[t];
    __syncthreads();
    #pragma unroll
    for (int d = 1; d < PN; d <<= 1) {
        int add = (t >= d) ? sscan[t - d] : 0;
        __syncthreads();
        sscan[t] += add;
        __syncthreads();
    }

    if (sflag[t]) {
        int rank = sscan[t] - 1;
        int gi = g * PK + rank;
        skeep[t] = gi;
        sperm[rank] = t;
        out[OFF_PERM + gi]  = (float)(g * PN + t);
        out[OFF_BATCH + gi] = (float)g;
    } else {
        skeep[t] = -1;
    }
    __syncthreads();

    // ---- Phase 7: x_out[gi] = x[perm] * tanh(score[perm])  — warp per row ----
    {
        const float4* xg = reinterpret_cast<const float4*>(x + (size_t)g * PN * PD);
        for (int row = warp; row < PK; row += 16) {
            int p = sperm[row];
            float tsc = tanhf(sscore[p]);
            const float4* xr = xg + (size_t)p * (PD / 4);
            float4* orow = reinterpret_cast<float4*>(
                out + OFF_X + (size_t)(g * PK + row) * PD);
            float4 a = xr[lane];
            float4 b = xr[lane + 32];
            a.x *= tsc; a.y *= tsc; a.z *= tsc; a.w *= tsc;
            b.x *= tsc; b.y *= tsc; b.z *= tsc; b.w *= tsc;
            orow[lane] = a;
            orow[lane + 32] = b;
        }
    }

    // ---- Phase 8: edge relabel + mask (no sync needed vs phase 7) ----
    {
        float4* oei_r = reinterpret_cast<float4*>(out + OFF_EI) + (size_t)g * (PEG / 4);
        float4* oei_c = reinterpret_cast<float4*>(out + OFF_EI + (size_t)PE) + (size_t)g * (PEG / 4);
        float4* omsk  = reinterpret_cast<float4*>(out + OFF_MASK) + (size_t)g * (PEG / 4);
        #pragma unroll
        for (int i = 0; i < PEG / 4 / PN; i++) {
            int idx = t + i * PN;
            int4 r = row4[idx];
            int4 c = col4[idx];
            int a0 = skeep[r.x & (PN - 1)], b0 = skeep[c.x & (PN - 1)];
            int a1 = skeep[r.y & (PN - 1)], b1 = skeep[c.y & (PN - 1)];
            int a2 = skeep[r.z & (PN - 1)], b2 = skeep[c.z & (PN - 1)];
            int a3 = skeep[r.w & (PN - 1)], b3 = skeep[c.w & (PN - 1)];
            bool m0 = (a0 >= 0) && (b0 >= 0);
            bool m1 = (a1 >= 0) && (b1 >= 0);
            bool m2 = (a2 >= 0) && (b2 >= 0);
            bool m3 = (a3 >= 0) && (b3 >= 0);
            float4 fr, fc, fm;
            fr.x = m0 ? (float)a0 : -1.0f; fc.x = m0 ? (float)b0 : -1.0f; fm.x = m0 ? 1.0f : 0.0f;
            fr.y = m1 ? (float)a1 : -1.0f; fc.y = m1 ? (float)b1 : -1.0f; fm.y = m1 ? 1.0f : 0.0f;
            fr.z = m2 ? (float)a2 : -1.0f; fc.z = m2 ? (float)b2 : -1.0f; fm.z = m2 ? 1.0f : 0.0f;
            fr.w = m3 ? (float)a3 : -1.0f; fc.w = m3 ? (float)b3 : -1.0f; fm.w = m3 ? 1.0f : 0.0f;
            oei_r[idx] = fr;
            oei_c[idx] = fc;
            omsk[idx]  = fm;
        }
    }
}

extern "C" void kernel_launch(void* const* d_in, const int* in_sizes, int n_in,
                              void* d_out, int out_size) {
    const float* x  = (const float*)d_in[0];
    const int*   ei = (const int*)d_in[1];
    const float* W  = (const float*)d_in[3];
    const float* b  = (const float*)d_in[4];
    float* out = (float*)d_out;

    k_fused<<<PB, PN>>>(x, ei, W, b, out);
}